// round 9
// baseline (speedup 1.0000x reference)
#include <cuda_runtime.h>
#include <cuda_fp16.h>
#include <stdint.h>
#include <math.h>

#define T_TOK 1024
#define H_DIM 2048
#define F_DIM 4096
#define E_EXP 8
#define ROWS_CAP 3072
#define MTILES (ROWS_CAP / 128)   // 24
#define KSPLIT 4

// A tiles: fp16, 128 rows x 32 halves, padded to 40 halves (20 words) per row
#define AP_W 20
#define AS_W (128 * AP_W)         // 2560 words
// GEMM1 B tiles: f32, 32 rows x 64, padded to 68 words
#define BP13 68
#define B13_W (32 * BP13)         // 2176 words
#define STG13_W (AS_W + 2 * B13_W)          // 6912
#define BT13_OFF (3 * STG13_W)              // 20736
#define BT13_BUF 3072                       // 2 mats x 64 cols x 24 words
#define SMEM13 ((BT13_OFF + 2 * BT13_BUF) * 4)   // 107520 B
// GEMM2 B tiles: f32, 32 rows x 128, padded to 132 words
#define BP2 132
#define B2_W (32 * BP2)           // 4224 words
#define STG2_W (AS_W + B2_W)                // 6784
#define BT2_OFF (3 * STG2_W)                // 20352
#define BT2_BUF 3072                        // 128 cols x 24 words
#define SMEM2 ((BT2_OFF + 2 * BT2_BUF) * 4)      // 105984 B

// ---------------- scratch ----------------
__device__ __align__(256) __half g_X[(size_t)ROWS_CAP * H_DIM];
__device__ __align__(256) __half g_A[(size_t)ROWS_CAP * F_DIM];
__device__ __align__(256) float  g_Y[(size_t)KSPLIT * ROWS_CAP * H_DIM];
__device__ int   g_off[E_EXP + 1];
__device__ int   g_tile_e[MTILES];
__device__ int   g_rows[ROWS_CAP];
__device__ float g_rw[ROWS_CAP];
__device__ int   g_pos[T_TOK * 2];
__device__ int   g_te[T_TOK * 2];
__device__ float g_tw[T_TOK * 2];

__device__ __forceinline__ float silu_f(float v) { return v / (1.0f + expf(-v)); }

__device__ __forceinline__ uint32_t smem_u32(const void* p) {
    uint32_t a;
    asm("{ .reg .u64 t; cvta.to.shared.u64 t, %1; cvt.u32.u64 %0, t; }" : "=r"(a) : "l"(p));
    return a;
}
__device__ __forceinline__ void cp16(uint32_t dst, const void* src) {
    asm volatile("cp.async.cg.shared.global [%0], [%1], 16;" :: "r"(dst), "l"(src));
}
#define CP_COMMIT() asm volatile("cp.async.commit_group;" ::: "memory")
#define CP_WAIT1()  asm volatile("cp.async.wait_group 1;" ::: "memory")

// pack two f32 -> half2 reg: lo = first arg, hi = second (PTX src1 = high half)
__device__ __forceinline__ uint32_t pack_h2(float lo, float hi) {
    uint32_t d;
    asm("cvt.rn.f16x2.f32 %0, %1, %2;" : "=r"(d) : "f"(hi), "f"(lo));
    return d;
}

__device__ __forceinline__ void ldsm4(uint32_t& r0, uint32_t& r1, uint32_t& r2, uint32_t& r3,
                                      uint32_t addr) {
    asm volatile("ldmatrix.sync.aligned.m8n8.x4.shared.b16 {%0,%1,%2,%3}, [%4];"
        : "=r"(r0), "=r"(r1), "=r"(r2), "=r"(r3) : "r"(addr));
}

__device__ __forceinline__ void mma_f16(float& c0, float& c1, float& c2, float& c3,
                                        uint32_t a0, uint32_t a1, uint32_t a2, uint32_t a3,
                                        uint32_t b0, uint32_t b1) {
    asm volatile(
        "mma.sync.aligned.m16n8k16.row.col.f32.f16.f16.f32 "
        "{%0,%1,%2,%3}, {%4,%5,%6,%7}, {%8,%9}, {%0,%1,%2,%3};\n"
        : "+f"(c0), "+f"(c1), "+f"(c2), "+f"(c3)
        : "r"(a0), "r"(a1), "r"(a2), "r"(a3), "r"(b0), "r"(b1));
}

// ------------------------------- routing -----------------------------------
__global__ void gate_kernel(const float* __restrict__ x, const float* __restrict__ wg) {
    int t = blockIdx.x * (blockDim.x >> 5) + (threadIdx.x >> 5);
    int lane = threadIdx.x & 31;
    if (t >= T_TOK) return;
    const float* xr = x + (size_t)t * H_DIM;
    float acc[E_EXP];
#pragma unroll
    for (int e = 0; e < E_EXP; e++) acc[e] = 0.0f;
    for (int h = lane; h < H_DIM; h += 32) {
        float xv = xr[h];
        const float* wr = wg + (size_t)h * E_EXP;
#pragma unroll
        for (int e = 0; e < E_EXP; e++) acc[e] += xv * wr[e];
    }
#pragma unroll
    for (int e = 0; e < E_EXP; e++)
#pragma unroll
        for (int o = 16; o > 0; o >>= 1) acc[e] += __shfl_xor_sync(0xffffffffu, acc[e], o);
    if (lane == 0) {
        int i0 = 0; float v0 = acc[0];
#pragma unroll
        for (int e = 1; e < E_EXP; e++) if (acc[e] > v0) { v0 = acc[e]; i0 = e; }
        int i1 = -1; float v1 = -INFINITY;
#pragma unroll
        for (int e = 0; e < E_EXP; e++) if (e != i0 && acc[e] > v1) { v1 = acc[e]; i1 = e; }
        float w0 = 1.0f / (1.0f + expf(v1 - v0));
        g_te[2 * t] = i0;     g_tw[2 * t] = w0;
        g_te[2 * t + 1] = i1; g_tw[2 * t + 1] = 1.0f - w0;
    }
}

__global__ void route_scatter_kernel() {
    __shared__ int scnt[E_EXP], soff[E_EXP + 1], sfill[E_EXP];
    int tid = threadIdx.x;
    if (tid < E_EXP) { scnt[tid] = 0; sfill[tid] = 0; }
    __syncthreads();
    for (int i = tid; i < 2 * T_TOK; i += 256) atomicAdd(&scnt[g_te[i]], 1);
    __syncthreads();
    if (tid == 0) {
        int o = 0;
#pragma unroll
        for (int e = 0; e < E_EXP; e++) { soff[e] = o; o += (scnt[e] + 127) & ~127; }
        soff[E_EXP] = o;
#pragma unroll
        for (int e = 0; e <= E_EXP; e++) g_off[e] = soff[e];
    }
    __syncthreads();
    if (tid < MTILES) {
        int e = -1;
#pragma unroll
        for (int ee = 0; ee < E_EXP; ee++)
            if (tid * 128 >= soff[ee] && tid * 128 < soff[ee + 1]) e = ee;
        g_tile_e[tid] = e;
    }
    for (int r = tid; r < ROWS_CAP; r += 256) {
        g_rows[r] = 0;
        g_rw[r] = 0.0f;
    }
    __syncthreads();
    for (int t = tid; t < T_TOK; t += 256) {
#pragma unroll
        for (int s = 0; s < 2; s++) {
            int e = g_te[2 * t + s];
            int r = soff[e] + atomicAdd(&sfill[e], 1);
            g_rows[r] = t;
            g_rw[r] = g_tw[2 * t + s];
            g_pos[2 * t + s] = r;
        }
    }
}

// gather x rows -> fp16 g_X
__global__ void gather_kernel(const float* __restrict__ x) {
    int idx = blockIdx.x * blockDim.x + threadIdx.x;
    int r = idx >> 9;
    if (r >= g_off[E_EXP]) return;
    int h = (idx & 511) << 2;
    float4 v = *reinterpret_cast<const float4*>(x + (size_t)g_rows[r] * H_DIM + h);
    *reinterpret_cast<__half2*>(g_X + (size_t)r * H_DIM + h) = __floats2half2_rn(v.x, v.y);
    *reinterpret_cast<__half2*>(g_X + (size_t)r * H_DIM + h + 2) = __floats2half2_rn(v.z, v.w);
}

// ---------------------------------------------------------------------------
// GEMM1 fused (fp16 mma): C1 = g_X@w1[e], C3 = g_X@w3[e];
// g_A = fp16(silu(C1)*C3*rw). Block 128x64x32, 8 warps (4M x 2N).
// Cooperative B f32->fp16 convert; A via ldmatrix; B frags via LDS.64.
// ---------------------------------------------------------------------------
__global__ __launch_bounds__(256, 2) void gemm13_kernel(const float* __restrict__ w1,
                                                        const float* __restrict__ w3) {
    extern __shared__ uint32_t smem[];

    const int my = blockIdx.y;
    const int e = g_tile_e[my];
    if (e < 0) return;

    const int tid = threadIdx.x;
    const int warp = tid >> 5;
    const int lane = tid & 31;
    const int wm = warp & 3;
    const int wn = warp >> 2;
    const int g = lane >> 2;
    const int tg = lane & 3;

    const int bm = my * 128;
    const int bn = blockIdx.x * 64;

    const float* B1g = w1 + (size_t)e * H_DIM * F_DIM;
    const float* B3g = w3 + (size_t)e * H_DIM * F_DIM;
    const uint32_t sbase = smem_u32(smem);

    const __half* a_src[2];
    uint32_t da[2];
#pragma unroll
    for (int i = 0; i < 2; i++) {
        int slot = tid + i * 256;
        int r = slot >> 2;
        int q = slot & 3;
        a_src[i] = g_X + (size_t)(bm + r) * H_DIM + q * 8;
        da[i] = (uint32_t)(r * AP_W * 4 + q * 16);
    }
    const float* b1_src[2];
    const float* b3_src[2];
    uint32_t db[2];
#pragma unroll
    for (int i = 0; i < 2; i++) {
        int slot = tid + i * 256;
        int r = slot >> 4;
        int c4 = (slot & 15) << 2;
        b1_src[i] = B1g + (size_t)r * F_DIM + bn + c4;
        b3_src[i] = B3g + (size_t)r * F_DIM + bn + c4;
        db[i] = (uint32_t)(AS_W + r * BP13 + c4) * 4u;
    }

    float c1[2][4][4], c3[2][4][4];
#pragma unroll
    for (int mi = 0; mi < 2; mi++)
#pragma unroll
        for (int ni = 0; ni < 4; ni++)
#pragma unroll
            for (int q = 0; q < 4; q++) { c1[mi][ni][q] = 0.0f; c3[mi][ni][q] = 0.0f; }

    const int kt = H_DIM / 32;  // 64

#pragma unroll
    for (int it = 0; it < 2; it++) {
        uint32_t ab = sbase + (uint32_t)it * (STG13_W * 4);
        int k0 = it * 32;
#pragma unroll
        for (int i = 0; i < 2; i++) cp16(ab + da[i], a_src[i] + k0);
#pragma unroll
        for (int i = 0; i < 2; i++) cp16(ab + db[i], b1_src[i] + (size_t)k0 * F_DIM);
#pragma unroll
        for (int i = 0; i < 2; i++) cp16(ab + db[i] + B13_W * 4, b3_src[i] + (size_t)k0 * F_DIM);
        CP_COMMIT();
    }

    // convert-pass constants
    const int cv_mat = warp >> 2;          // 0 -> b1, 1 -> b3
    const int cv_cb = (warp & 3) * 16;
    // ldmatrix constants
    const int arow = wm * 32 + (lane & 15);
    const int akoff = (lane >> 4) * 8;     // halves

    for (int it = 0; it < kt; it++) {
        const int stg = it % 3;
        CP_WAIT1();
        __syncthreads();

        if (it + 2 < kt) {
            int nt = it + 2;
            uint32_t ab = sbase + (uint32_t)(nt % 3) * (STG13_W * 4);
            int k0 = nt * 32;
#pragma unroll
            for (int i = 0; i < 2; i++) cp16(ab + da[i], a_src[i] + k0);
#pragma unroll
            for (int i = 0; i < 2; i++) cp16(ab + db[i], b1_src[i] + (size_t)k0 * F_DIM);
#pragma unroll
            for (int i = 0; i < 2; i++) cp16(ab + db[i] + B13_W * 4, b3_src[i] + (size_t)k0 * F_DIM);
            CP_COMMIT();
        }

        // cooperative convert: f32 B stage -> fp16 interleaved Bt (ping-pong)
        {
            const float* src = (const float*)(smem + stg * STG13_W + AS_W) + cv_mat * B13_W;
            uint32_t* dst = smem + BT13_OFF + (it & 1) * BT13_BUF + cv_mat * 1536;
#pragma unroll
            for (int p = 0; p < 2; p++) {
                int col = cv_cb + p * 8 + g;
#pragma unroll
                for (int i = 0; i < 4; i++) {
                    int o = tg + 4 * i;
                    int n = 8 * (i >> 1) + 2 * tg + (i & 1);
                    float f0 = src[(2 * o) * BP13 + col];
                    float f1 = src[(2 * o + 1) * BP13 + col];
                    dst[col * 24 + n] = pack_h2(f0, f1);
                }
            }
        }
        __syncthreads();

        const uint32_t abase = sbase + (uint32_t)stg * (STG13_W * 4);
        const uint32_t* Bt1 = smem + BT13_OFF + (it & 1) * BT13_BUF;
        const uint32_t* Bt3 = Bt1 + 1536;

#pragma unroll
        for (int ks = 0; ks < 2; ks++) {
            uint32_t a[2][4];
#pragma unroll
            for (int mi = 0; mi < 2; mi++) {
                uint32_t ad = abase + (uint32_t)((arow + mi * 16) * 40 + ks * 16 + akoff) * 2;
                ldsm4(a[mi][0], a[mi][1], a[mi][2], a[mi][3], ad);
            }
#pragma unroll
            for (int ni = 0; ni < 4; ni++) {
                int col = wn * 32 + ni * 8 + g;
                uint2 b1v = *reinterpret_cast<const uint2*>(Bt1 + col * 24 + ks * 8 + 2 * tg);
                uint2 b3v = *reinterpret_cast<const uint2*>(Bt3 + col * 24 + ks * 8 + 2 * tg);
#pragma unroll
                for (int mi = 0; mi < 2; mi++) {
                    mma_f16(c1[mi][ni][0], c1[mi][ni][1], c1[mi][ni][2], c1[mi][ni][3],
                            a[mi][0], a[mi][1], a[mi][2], a[mi][3], b1v.x, b1v.y);
                    mma_f16(c3[mi][ni][0], c3[mi][ni][1], c3[mi][ni][2], c3[mi][ni][3],
                            a[mi][0], a[mi][1], a[mi][2], a[mi][3], b3v.x, b3v.y);
                }
            }
        }
    }

    const int r_base = bm + wm * 32;
    const int c_base = bn + wn * 32;
#pragma unroll
    for (int mi = 0; mi < 2; mi++) {
        int r0 = r_base + mi * 16 + g;
        float wa = g_rw[r0];
        float wb = g_rw[r0 + 8];
        size_t o0 = (size_t)r0 * F_DIM;
        size_t o1 = (size_t)(r0 + 8) * F_DIM;
#pragma unroll
        for (int ni = 0; ni < 4; ni++) {
            int cl = c_base + ni * 8 + 2 * tg;
            __half2 v0 = __floats2half2_rn(silu_f(c1[mi][ni][0]) * c3[mi][ni][0] * wa,
                                           silu_f(c1[mi][ni][1]) * c3[mi][ni][1] * wa);
            __half2 v1 = __floats2half2_rn(silu_f(c1[mi][ni][2]) * c3[mi][ni][2] * wb,
                                           silu_f(c1[mi][ni][3]) * c3[mi][ni][3] * wb);
            *reinterpret_cast<__half2*>(g_A + o0 + cl) = v0;
            *reinterpret_cast<__half2*>(g_A + o1 + cl) = v1;
        }
    }
}

// ---------------------------------------------------------------------------
// GEMM2 (fp16 mma): g_Y[z] = g_A(:, z-quarter) @ w2[e](z-quarter, :).
// Block 128x128x32, K-split 4. Same cooperative-convert structure.
// ---------------------------------------------------------------------------
__global__ __launch_bounds__(256, 2) void gemm2_kernel(const float* __restrict__ w2) {
    extern __shared__ uint32_t smem[];

    const int my = blockIdx.y;
    const int e = g_tile_e[my];
    if (e < 0) return;
    const int z = blockIdx.z;

    const int tid = threadIdx.x;
    const int warp = tid >> 5;
    const int lane = tid & 31;
    const int wm = warp & 3;
    const int wn = warp >> 2;
    const int g = lane >> 2;
    const int tg = lane & 3;

    const int bm = my * 128;
    const int bn = blockIdx.x * 128;
    const int kseg = F_DIM / KSPLIT;   // 1024

    const __half* Abase = g_A + (size_t)z * kseg;
    const float* Bbase = w2 + (size_t)e * F_DIM * H_DIM + (size_t)z * kseg * H_DIM;
    const uint32_t sbase = smem_u32(smem);

    const __half* a_src[2];
    uint32_t da[2];
#pragma unroll
    for (int i = 0; i < 2; i++) {
        int slot = tid + i * 256;
        int r = slot >> 2;
        int q = slot & 3;
        a_src[i] = Abase + (size_t)(bm + r) * F_DIM + q * 8;
        da[i] = (uint32_t)(r * AP_W * 4 + q * 16);
    }
    const float* b_src[4];
    uint32_t db[4];
#pragma unroll
    for (int i = 0; i < 4; i++) {
        int slot = tid + i * 256;
        int r = slot >> 5;
        int c4 = (slot & 31) << 2;
        b_src[i] = Bbase + (size_t)r * H_DIM + bn + c4;
        db[i] = (uint32_t)(AS_W + r * BP2 + c4) * 4u;
    }

    float c[2][8][4];
#pragma unroll
    for (int mi = 0; mi < 2; mi++)
#pragma unroll
        for (int ni = 0; ni < 8; ni++)
#pragma unroll
            for (int q = 0; q < 4; q++) c[mi][ni][q] = 0.0f;

    const int kt = kseg / 32;   // 32

#pragma unroll
    for (int it = 0; it < 2; it++) {
        uint32_t ab = sbase + (uint32_t)it * (STG2_W * 4);
        int k0 = it * 32;
#pragma unroll
        for (int i = 0; i < 2; i++) cp16(ab + da[i], a_src[i] + k0);
#pragma unroll
        for (int i = 0; i < 4; i++) cp16(ab + db[i], b_src[i] + (size_t)k0 * H_DIM);
        CP_COMMIT();
    }

    const int cv_cb = warp * 16;
    const int arow = wm * 32 + (lane & 15);
    const int akoff = (lane >> 4) * 8;

    for (int it = 0; it < kt; it++) {
        const int stg = it % 3;
        CP_WAIT1();
        __syncthreads();

        if (it + 2 < kt) {
            int nt = it + 2;
            uint32_t ab = sbase + (uint32_t)(nt % 3) * (STG2_W * 4);
            int k0 = nt * 32;
#pragma unroll
            for (int i = 0; i < 2; i++) cp16(ab + da[i], a_src[i] + k0);
#pragma unroll
            for (int i = 0; i < 4; i++) cp16(ab + db[i], b_src[i] + (size_t)k0 * H_DIM);
            CP_COMMIT();
        }

        {
            const float* src = (const float*)(smem + stg * STG2_W + AS_W);
            uint32_t* dst = smem + BT2_OFF + (it & 1) * BT2_BUF;
#pragma unroll
            for (int p = 0; p < 2; p++) {
                int col = cv_cb + p * 8 + g;
#pragma unroll
                for (int i = 0; i < 4; i++) {
                    int o = tg + 4 * i;
                    int n = 8 * (i >> 1) + 2 * tg + (i & 1);
                    float f0 = src[(2 * o) * BP2 + col];
                    float f1 = src[(2 * o + 1) * BP2 + col];
                    dst[col * 24 + n] = pack_h2(f0, f1);
                }
            }
        }
        __syncthreads();

        const uint32_t abase = sbase + (uint32_t)stg * (STG2_W * 4);
        const uint32_t* Bt = smem + BT2_OFF + (it & 1) * BT2_BUF;

#pragma unroll
        for (int ks = 0; ks < 2; ks++) {
            uint32_t a[2][4];
#pragma unroll
            for (int mi = 0; mi < 2; mi++) {
                uint32_t ad = abase + (uint32_t)((arow + mi * 16) * 40 + ks * 16 + akoff) * 2;
                ldsm4(a[mi][0], a[mi][1], a[mi][2], a[mi][3], ad);
            }
#pragma unroll
            for (int ni = 0; ni < 8; ni++) {
                int col = wn * 64 + ni * 8 + g;
                uint2 bv = *reinterpret_cast<const uint2*>(Bt + col * 24 + ks * 8 + 2 * tg);
#pragma unroll
                for (int mi = 0; mi < 2; mi++)
                    mma_f16(c[mi][ni][0], c[mi][ni][1], c[mi][ni][2], c[mi][ni][3],
                            a[mi][0], a[mi][1], a[mi][2], a[mi][3], bv.x, bv.y);
            }
        }
    }

    float* Yp = g_Y + (size_t)z * ((size_t)ROWS_CAP * H_DIM);
    const int r_base = bm + wm * 32;
    const int c_base = bn + wn * 64;
#pragma unroll
    for (int mi = 0; mi < 2; mi++) {
        int r0 = r_base + mi * 16 + g;
        size_t o0 = (size_t)r0 * H_DIM;
        size_t o1 = (size_t)(r0 + 8) * H_DIM;
#pragma unroll
        for (int ni = 0; ni < 8; ni++) {
            int cl = c_base + ni * 8 + 2 * tg;
            *reinterpret_cast<float2*>(Yp + o0 + cl) = make_float2(c[mi][ni][0], c[mi][ni][1]);
            *reinterpret_cast<float2*>(Yp + o1 + cl) = make_float2(c[mi][ni][2], c[mi][ni][3]);
        }
    }
}

// out[t] = sum over (slot, kslice) — fixed order, deterministic
__global__ void combine_kernel(float* __restrict__ out) {
    int i = blockIdx.x * blockDim.x + threadIdx.x;
    int t = i >> 9;
    int h = (i & 511) << 2;
    size_t r0 = (size_t)g_pos[2 * t] * H_DIM + h;
    size_t r1 = (size_t)g_pos[2 * t + 1] * H_DIM + h;
    const size_t SL = (size_t)ROWS_CAP * H_DIM;
    float4 s0 = make_float4(0.f, 0.f, 0.f, 0.f);
    float4 s1 = make_float4(0.f, 0.f, 0.f, 0.f);
#pragma unroll
    for (int zz = 0; zz < KSPLIT; zz++) {
        float4 a = *reinterpret_cast<const float4*>(g_Y + zz * SL + r0);
        float4 b = *reinterpret_cast<const float4*>(g_Y + zz * SL + r1);
        s0.x += a.x; s0.y += a.y; s0.z += a.z; s0.w += a.w;
        s1.x += b.x; s1.y += b.y; s1.z += b.z; s1.w += b.w;
    }
    *reinterpret_cast<float4*>(out + (size_t)t * H_DIM + h) =
        make_float4(s0.x + s1.x, s0.y + s1.y, s0.z + s1.z, s0.w + s1.w);
}

extern "C" void kernel_launch(void* const* d_in, const int* in_sizes, int n_in,
                              void* d_out, int out_size) {
    const float* x  = (const float*)d_in[0];
    const float* wg = (const float*)d_in[1];
    const float* w1 = (const float*)d_in[2];
    const float* w3 = (const float*)d_in[3];
    const float* w2 = (const float*)d_in[4];
    float* out = (float*)d_out;

    cudaFuncSetAttribute(gemm13_kernel, cudaFuncAttributeMaxDynamicSharedMemorySize, SMEM13);
    cudaFuncSetAttribute(gemm2_kernel, cudaFuncAttributeMaxDynamicSharedMemorySize, SMEM2);

    gate_kernel<<<T_TOK / 8, 256>>>(x, wg);
    route_scatter_kernel<<<1, 256>>>();
    gather_kernel<<<ROWS_CAP * 512 / 256, 256>>>(x);

    dim3 g1(F_DIM / 64, MTILES);
    gemm13_kernel<<<g1, 256, SMEM13>>>(w1, w3);

    dim3 g2(H_DIM / 128, MTILES, KSPLIT);
    gemm2_kernel<<<g2, 256, SMEM2>>>(w2);

    combine_kernel<<<(T_TOK * H_DIM / 4) / 256, 256>>>(out);
}